// round 1
// baseline (speedup 1.0000x reference)
#include <cuda_runtime.h>
#include <math.h>

// ---------------- problem constants ----------------
constexpr int BB   = 16;
constexpr int PP   = 2048;
constexpr int DD   = 512;
constexpr int HH   = 8;
constexpr int CC   = 64;
constexpr int HD   = 64;
constexpr int FFNI = 1024;
constexpr int FFNH = 4096;
constexpr int MT   = BB * PP;      // 32768 rows

// ---------------- scratch (device globals, alloc-free) ----------------
__device__ float g_q    [MT * DD];                 // 64 MB
__device__ float g_aff  [BB * HH * CC * PP];       // 64 MB
__device__ float g_c2p  [BB * HH * CC * PP];       // 64 MB
__device__ float g_p2c  [BB * HH * CC * PP];       // 64 MB
__device__ float g_vcore[BB * HH * CC * HD];       // 2 MB
__device__ float g_vout [MT * DD];                 // 64 MB
__device__ float g_ffnin[MT * FFNI];               // 128 MB
__device__ float g_hid  [(size_t)MT * FFNH];       // 512 MB
__device__ float g_pre  [MT * DD];                 // 64 MB

// ---------------- helpers ----------------
__device__ __forceinline__ float to_tf32(float x) {
    unsigned u;
    asm("cvt.rna.tf32.f32 %0, %1;" : "=r"(u) : "f"(x));
    return __uint_as_float(u);
}

__device__ __forceinline__ void mma_tf32(float d[4], const float a[4], const float b[2]) {
    asm volatile(
        "mma.sync.aligned.m16n8k8.row.col.f32.tf32.tf32.f32 "
        "{%0,%1,%2,%3}, {%4,%5,%6,%7}, {%8,%9}, {%0,%1,%2,%3};\n"
        : "+f"(d[0]), "+f"(d[1]), "+f"(d[2]), "+f"(d[3])
        : "r"(__float_as_uint(a[0])), "r"(__float_as_uint(a[1])),
          "r"(__float_as_uint(a[2])), "r"(__float_as_uint(a[3])),
          "r"(__float_as_uint(b[0])), "r"(__float_as_uint(b[1])));
}

__device__ __forceinline__ float gelu_f(float x) {
    return 0.5f * x * (1.0f + erff(x * 0.70710678118654752f));
}

// ---------------- TF32 GEMM: C = epi(A[M,K] @ B[K,N] + bias) ----------------
// EPI: 0 = bias only, 1 = bias + exact GELU, 2 = bias + residual(res)
template <int EPI>
__global__ __launch_bounds__(256, 1) void gemm_tf32_kernel(
    const float* __restrict__ A, const float* __restrict__ Bm,
    const float* __restrict__ bias, const float* __restrict__ res,
    float* __restrict__ Cout, int Mg, int Ng, int Kg)
{
    __shared__ __align__(16) float As[2][16][132];   // [k][m] transposed
    __shared__ __align__(16) float Bs[2][16][132];   // [k][n]

    const int t    = threadIdx.x;
    const int lane = t & 31, warp = t >> 5;
    const int wm   = warp & 3, wn = warp >> 2;       // 4 x 2 warp grid
    const int g    = lane >> 2, tig = lane & 3;
    const int bm   = blockIdx.y << 7, bn = blockIdx.x << 7;

    int arow[2], akc[2], brow[2], bcol[2];
#pragma unroll
    for (int i = 0; i < 2; i++) {
        int v = t + (i << 8);
        arow[i] = v >> 2;  akc[i]  = (v & 3) << 2;
        brow[i] = v >> 5;  bcol[i] = (v & 31) << 2;
    }

    float acc[2][8][4];
#pragma unroll
    for (int mt = 0; mt < 2; mt++)
#pragma unroll
        for (int nt = 0; nt < 8; nt++)
#pragma unroll
            for (int r = 0; r < 4; r++) acc[mt][nt][r] = 0.0f;

    float4 afr[2], bfr[2];
#pragma unroll
    for (int i = 0; i < 2; i++) {
        afr[i] = *(const float4*)(A  + (size_t)(bm + arow[i]) * Kg + akc[i]);
        bfr[i] = *(const float4*)(Bm + (size_t)brow[i] * Ng + bn + bcol[i]);
    }
#pragma unroll
    for (int i = 0; i < 2; i++) {
        As[0][akc[i] + 0][arow[i]] = to_tf32(afr[i].x);
        As[0][akc[i] + 1][arow[i]] = to_tf32(afr[i].y);
        As[0][akc[i] + 2][arow[i]] = to_tf32(afr[i].z);
        As[0][akc[i] + 3][arow[i]] = to_tf32(afr[i].w);
        float4 bb = make_float4(to_tf32(bfr[i].x), to_tf32(bfr[i].y),
                                to_tf32(bfr[i].z), to_tf32(bfr[i].w));
        *(float4*)&Bs[0][brow[i]][bcol[i]] = bb;
    }
    __syncthreads();

    const int KT = Kg >> 4;
    int cur = 0;
    for (int kt = 0; kt < KT; kt++) {
        if (kt + 1 < KT) {
            int ko = (kt + 1) << 4;
#pragma unroll
            for (int i = 0; i < 2; i++) {
                afr[i] = *(const float4*)(A  + (size_t)(bm + arow[i]) * Kg + ko + akc[i]);
                bfr[i] = *(const float4*)(Bm + (size_t)(ko + brow[i]) * Ng + bn + bcol[i]);
            }
        }
#pragma unroll
        for (int kk = 0; kk < 16; kk += 8) {
            float af[2][4], bf[8][2];
#pragma unroll
            for (int mt = 0; mt < 2; mt++) {
                int rb = (wm << 5) + (mt << 4);
                af[mt][0] = As[cur][kk + tig    ][rb + g    ];
                af[mt][1] = As[cur][kk + tig    ][rb + g + 8];
                af[mt][2] = As[cur][kk + tig + 4][rb + g    ];
                af[mt][3] = As[cur][kk + tig + 4][rb + g + 8];
            }
#pragma unroll
            for (int nt = 0; nt < 8; nt++) {
                int cb = (wn << 6) + (nt << 3) + g;
                bf[nt][0] = Bs[cur][kk + tig    ][cb];
                bf[nt][1] = Bs[cur][kk + tig + 4][cb];
            }
#pragma unroll
            for (int mt = 0; mt < 2; mt++)
#pragma unroll
                for (int nt = 0; nt < 8; nt++)
                    mma_tf32(acc[mt][nt], af[mt], bf[nt]);
        }
        if (kt + 1 < KT) {
            int nxt = cur ^ 1;
#pragma unroll
            for (int i = 0; i < 2; i++) {
                As[nxt][akc[i] + 0][arow[i]] = to_tf32(afr[i].x);
                As[nxt][akc[i] + 1][arow[i]] = to_tf32(afr[i].y);
                As[nxt][akc[i] + 2][arow[i]] = to_tf32(afr[i].z);
                As[nxt][akc[i] + 3][arow[i]] = to_tf32(afr[i].w);
                float4 bb = make_float4(to_tf32(bfr[i].x), to_tf32(bfr[i].y),
                                        to_tf32(bfr[i].z), to_tf32(bfr[i].w));
                *(float4*)&Bs[nxt][brow[i]][bcol[i]] = bb;
            }
            __syncthreads();
            cur = nxt;
        }
    }

    // epilogue
#pragma unroll
    for (int mt = 0; mt < 2; mt++) {
#pragma unroll
        for (int nt = 0; nt < 8; nt++) {
            int r0 = bm + (wm << 5) + (mt << 4) + g;
            int c0 = bn + (wn << 6) + (nt << 3) + (tig << 1);
            float b0 = bias[c0], b1 = bias[c0 + 1];
            float v00 = acc[mt][nt][0] + b0, v01 = acc[mt][nt][1] + b1;
            float v10 = acc[mt][nt][2] + b0, v11 = acc[mt][nt][3] + b1;
            if (EPI == 1) {
                v00 = gelu_f(v00); v01 = gelu_f(v01);
                v10 = gelu_f(v10); v11 = gelu_f(v11);
            }
            if (EPI == 2) {
                const float* r0p = res + (size_t)r0 * Ng + c0;
                const float* r1p = res + (size_t)(r0 + 8) * Ng + c0;
                v00 += r0p[0]; v01 += r0p[1];
                v10 += r1p[0]; v11 += r1p[1];
            }
            float2 o0 = make_float2(v00, v01);
            float2 o1 = make_float2(v10, v11);
            *(float2*)(Cout + (size_t)r0 * Ng + c0)       = o0;
            *(float2*)(Cout + (size_t)(r0 + 8) * Ng + c0) = o1;
        }
    }
}

// ---------------- affinity: aff[b,h,c,p] = (1/8) * cores[h,c,:]·q[b,p,h,:] ----------------
__global__ __launch_bounds__(256) void aff_kernel(
    const float* __restrict__ q, const float* __restrict__ cores, float* __restrict__ aff)
{
    __shared__ __align__(16) float cs[64][68];   // [c][hd]
    __shared__ __align__(16) float qs[64][68];   // [p][hd]
    const int bh = blockIdx.y, b = bh >> 3, h = bh & 7;
    const int p0 = blockIdx.x << 6;
    const int t  = threadIdx.x;

#pragma unroll
    for (int i = 0; i < 4; i++) {
        int v = t + (i << 8);
        int r = v >> 4, c4 = (v & 15) << 2;
        *(float4*)&cs[r][c4] = *(const float4*)(cores + ((h * 64 + r) * 64 + c4));
        *(float4*)&qs[r][c4] = *(const float4*)(q + (size_t)(b * 2048 + p0 + r) * 512 + h * 64 + c4);
    }
    __syncthreads();

    const int c4 = (t >> 4) << 2, p4 = (t & 15) << 2;
    float acc[4][4] = {};
#pragma unroll
    for (int k = 0; k < 64; k++) {
        float a[4], bq[4];
#pragma unroll
        for (int i = 0; i < 4; i++) { a[i] = cs[c4 + i][k]; bq[i] = qs[p4 + i][k]; }
#pragma unroll
        for (int i = 0; i < 4; i++)
#pragma unroll
            for (int j = 0; j < 4; j++) acc[i][j] += a[i] * bq[j];
    }
#pragma unroll
    for (int i = 0; i < 4; i++) {
        float4 o = make_float4(acc[i][0] * 0.125f, acc[i][1] * 0.125f,
                               acc[i][2] * 0.125f, acc[i][3] * 0.125f);
        *(float4*)(aff + (size_t)(bh * 64 + c4 + i) * 2048 + p0 + p4) = o;
    }
}

// ---------------- softmax over p (rows of 2048) ----------------
__global__ __launch_bounds__(256) void softmax_p_kernel(
    const float* __restrict__ aff, float* __restrict__ out)
{
    const int row = blockIdx.x;
    const int t = threadIdx.x, lane = t & 31, warp = t >> 5;
    const float4* src = (const float4*)(aff + (size_t)row * 2048);
    float4* dst = (float4*)(out + (size_t)row * 2048);
    __shared__ float red[8];

    float4 x0 = src[t], x1 = src[t + 256];
    float m = fmaxf(fmaxf(fmaxf(x0.x, x0.y), fmaxf(x0.z, x0.w)),
                    fmaxf(fmaxf(x1.x, x1.y), fmaxf(x1.z, x1.w)));
#pragma unroll
    for (int o = 16; o; o >>= 1) m = fmaxf(m, __shfl_xor_sync(0xffffffffu, m, o));
    if (lane == 0) red[warp] = m;
    __syncthreads();
    float M = red[0];
#pragma unroll
    for (int w = 1; w < 8; w++) M = fmaxf(M, red[w]);
    __syncthreads();

    float4 e0, e1;
    e0.x = expf(x0.x - M); e0.y = expf(x0.y - M); e0.z = expf(x0.z - M); e0.w = expf(x0.w - M);
    e1.x = expf(x1.x - M); e1.y = expf(x1.y - M); e1.z = expf(x1.z - M); e1.w = expf(x1.w - M);
    float s = e0.x + e0.y + e0.z + e0.w + e1.x + e1.y + e1.z + e1.w;
#pragma unroll
    for (int o = 16; o; o >>= 1) s += __shfl_xor_sync(0xffffffffu, s, o);
    if (lane == 0) red[warp] = s;
    __syncthreads();
    float S = 0.0f;
#pragma unroll
    for (int w = 0; w < 8; w++) S += red[w];
    float inv = 1.0f / S;

    dst[t]       = make_float4(e0.x * inv, e0.y * inv, e0.z * inv, e0.w * inv);
    dst[t + 256] = make_float4(e1.x * inv, e1.y * inv, e1.z * inv, e1.w * inv);
}

// ---------------- softmax over c (64-long, strided) ----------------
__global__ __launch_bounds__(256) void softmax_c_kernel(
    const float* __restrict__ aff, float* __restrict__ out)
{
    const int bh = blockIdx.y;
    const int p  = (blockIdx.x << 8) + threadIdx.x;
    const float* src = aff + (size_t)bh * 64 * 2048 + p;
    float* dst = out + (size_t)bh * 64 * 2048 + p;

    float vals[64];
    float m = -1e30f;
#pragma unroll
    for (int c = 0; c < 64; c++) { vals[c] = src[c * 2048]; m = fmaxf(m, vals[c]); }
    float s = 0.0f;
#pragma unroll
    for (int c = 0; c < 64; c++) { vals[c] = expf(vals[c] - m); s += vals[c]; }
    float inv = 1.0f / s;
#pragma unroll
    for (int c = 0; c < 64; c++) dst[c * 2048] = vals[c] * inv;
}

// ---------------- v_core[b,h,c,hd] = sum_p input[b,p,h,hd] * c2p[b,h,c,p] ----------------
__global__ __launch_bounds__(256) void vcore_kernel(
    const float* __restrict__ input, const float* __restrict__ c2p, float* __restrict__ vcore)
{
    __shared__ __align__(16) float a_s[64][68];  // [c][p]
    __shared__ __align__(16) float v_s[64][68];  // [p][hd]
    const int bh = blockIdx.x, b = bh >> 3, h = bh & 7;
    const int t = threadIdx.x;
    const int c4 = (t >> 4) << 2, d4 = (t & 15) << 2;

    float acc[4][4] = {};
    for (int pt = 0; pt < 2048; pt += 64) {
#pragma unroll
        for (int i = 0; i < 4; i++) {
            int v = t + (i << 8);
            int r = v >> 4, k4 = (v & 15) << 2;
            *(float4*)&a_s[r][k4] = *(const float4*)(c2p + (size_t)(bh * 64 + r) * 2048 + pt + k4);
            *(float4*)&v_s[r][k4] = *(const float4*)(input + (size_t)(b * 2048 + pt + r) * 512 + h * 64 + k4);
        }
        __syncthreads();
#pragma unroll
        for (int k = 0; k < 64; k++) {
            float a[4], vv[4];
#pragma unroll
            for (int i = 0; i < 4; i++) { a[i] = a_s[c4 + i][k]; vv[i] = v_s[k][d4 + i]; }
#pragma unroll
            for (int i = 0; i < 4; i++)
#pragma unroll
                for (int j = 0; j < 4; j++) acc[i][j] += a[i] * vv[j];
        }
        __syncthreads();
    }
#pragma unroll
    for (int i = 0; i < 4; i++) {
        float4 o = make_float4(acc[i][0], acc[i][1], acc[i][2], acc[i][3]);
        *(float4*)(vcore + (size_t)(bh * 64 + c4 + i) * 64 + d4) = o;
    }
}

// ---------------- v_out[b,p,h*64+hd] = sum_c vcore[b,h,c,hd] * p2c[b,h,c,p] ----------------
__global__ __launch_bounds__(256) void vpatch_kernel(
    const float* __restrict__ vcore, const float* __restrict__ p2c, float* __restrict__ vout)
{
    __shared__ __align__(16) float vc_s[64][68]; // [c][hd]
    __shared__ __align__(16) float pc_s[64][68]; // [c][p]
    const int bh = blockIdx.y, b = bh >> 3, h = bh & 7;
    const int p0 = blockIdx.x << 6;
    const int t = threadIdx.x;

#pragma unroll
    for (int i = 0; i < 4; i++) {
        int v = t + (i << 8);
        int r = v >> 4, k4 = (v & 15) << 2;
        *(float4*)&vc_s[r][k4] = *(const float4*)(vcore + (size_t)(bh * 64 + r) * 64 + k4);
        *(float4*)&pc_s[r][k4] = *(const float4*)(p2c + (size_t)(bh * 64 + r) * 2048 + p0 + k4);
    }
    __syncthreads();

    const int p4 = (t & 15) << 2, d4 = (t >> 4) << 2;
    float acc[4][4] = {};  // [p][hd]
#pragma unroll
    for (int c = 0; c < 64; c++) {
        float a[4], vv[4];
#pragma unroll
        for (int i = 0; i < 4; i++) { a[i] = pc_s[c][p4 + i]; vv[i] = vc_s[c][d4 + i]; }
#pragma unroll
        for (int i = 0; i < 4; i++)
#pragma unroll
            for (int j = 0; j < 4; j++) acc[i][j] += a[i] * vv[j];
    }
#pragma unroll
    for (int i = 0; i < 4; i++) {
        float4 o = make_float4(acc[i][0], acc[i][1], acc[i][2], acc[i][3]);
        *(float4*)(vout + (size_t)(b * 2048 + p0 + p4 + i) * 512 + h * 64 + d4) = o;
    }
}

// ---------------- ffn_in = [input - vout, vout] ----------------
__global__ __launch_bounds__(256) void ffnin_kernel(
    const float* __restrict__ input, const float* __restrict__ vout, float* __restrict__ ffnin)
{
    int i = blockIdx.x * 256 + threadIdx.x;     // float4 index over MT*512/4
    int row = i >> 7, c4 = (i & 127) << 2;
    float4 x = *(const float4*)(input + (size_t)i * 4);
    float4 v = *(const float4*)(vout + (size_t)i * 4);
    float4 d = make_float4(x.x - v.x, x.y - v.y, x.z - v.z, x.w - v.w);
    *(float4*)(ffnin + (size_t)row * 1024 + c4)       = d;
    *(float4*)(ffnin + (size_t)row * 1024 + 512 + c4) = v;
}

// ---------------- LayerNorm over D=512 ----------------
__global__ __launch_bounds__(128) void ln_kernel(
    const float* __restrict__ pre, const float* __restrict__ gamma,
    const float* __restrict__ beta, float* __restrict__ out)
{
    const int row = blockIdx.x;
    const int t = threadIdx.x, lane = t & 31, warp = t >> 5;
    __shared__ float rs[4], rs2[4];

    float4 x = *(const float4*)(pre + (size_t)row * 512 + t * 4);
    float s  = x.x + x.y + x.z + x.w;
    float s2 = x.x * x.x + x.y * x.y + x.z * x.z + x.w * x.w;
#pragma unroll
    for (int o = 16; o; o >>= 1) {
        s  += __shfl_xor_sync(0xffffffffu, s, o);
        s2 += __shfl_xor_sync(0xffffffffu, s2, o);
    }
    if (lane == 0) { rs[warp] = s; rs2[warp] = s2; }
    __syncthreads();
    float S = rs[0] + rs[1] + rs[2] + rs[3];
    float S2 = rs2[0] + rs2[1] + rs2[2] + rs2[3];
    float mean = S * (1.0f / 512.0f);
    float var  = S2 * (1.0f / 512.0f) - mean * mean;
    float rstd = rsqrtf(var + 1e-5f);

    float4 gm = *(const float4*)(gamma + t * 4);
    float4 bt = *(const float4*)(beta + t * 4);
    float4 o;
    o.x = (x.x - mean) * rstd * gm.x + bt.x;
    o.y = (x.y - mean) * rstd * gm.y + bt.y;
    o.z = (x.z - mean) * rstd * gm.z + bt.z;
    o.w = (x.w - mean) * rstd * gm.w + bt.w;
    *(float4*)(out + (size_t)row * 512 + t * 4) = o;
}

// ---------------- launch ----------------
extern "C" void kernel_launch(void* const* d_in, const int* in_sizes, int n_in,
                              void* d_out, int out_size)
{
    const float* input = (const float*)d_in[0];
    const float* cores = (const float*)d_in[1];
    const float* Wv    = (const float*)d_in[2];
    const float* bv    = (const float*)d_in[3];
    const float* W1    = (const float*)d_in[4];
    const float* b1    = (const float*)d_in[5];
    const float* W2    = (const float*)d_in[6];
    const float* b2    = (const float*)d_in[7];
    const float* gamma = (const float*)d_in[8];
    const float* beta  = (const float*)d_in[9];
    float* out = (float*)d_out;

    float *pq, *paff, *pc2p, *pp2c, *pvc, *pvo, *pfi, *phid, *ppre;
    cudaGetSymbolAddress((void**)&pq,   g_q);
    cudaGetSymbolAddress((void**)&paff, g_aff);
    cudaGetSymbolAddress((void**)&pc2p, g_c2p);
    cudaGetSymbolAddress((void**)&pp2c, g_p2c);
    cudaGetSymbolAddress((void**)&pvc,  g_vcore);
    cudaGetSymbolAddress((void**)&pvo,  g_vout);
    cudaGetSymbolAddress((void**)&pfi,  g_ffnin);
    cudaGetSymbolAddress((void**)&phid, g_hid);
    cudaGetSymbolAddress((void**)&ppre, g_pre);

    // 1. q = input @ Wv + bv
    gemm_tf32_kernel<0><<<dim3(DD / 128, MT / 128), 256>>>(input, Wv, bv, nullptr, pq, MT, DD, DD);
    // 2. affinity
    aff_kernel<<<dim3(PP / 64, BB * HH), 256>>>(pq, cores, paff);
    // 3. softmax over patches
    softmax_p_kernel<<<BB * HH * CC, 256>>>(paff, pc2p);
    // 4. softmax over cores
    softmax_c_kernel<<<dim3(PP / 256, BB * HH), 256>>>(paff, pp2c);
    // 5. aggregate patches -> cores
    vcore_kernel<<<BB * HH, 256>>>(input, pc2p, pvc);
    // 6. redistribute cores -> patches
    vpatch_kernel<<<dim3(PP / 64, BB * HH), 256>>>(pvc, pp2c, pvo);
    // 7. ffn_in = [input - vout, vout]
    ffnin_kernel<<<(MT * DD / 4) / 256, 256>>>(input, pvo, pfi);
    // 8. hid = gelu(ffn_in @ W1 + b1)
    gemm_tf32_kernel<1><<<dim3(FFNH / 128, MT / 128), 256>>>(pfi, W1, b1, nullptr, phid, MT, FFNH, FFNI);
    // 9. pre = input + hid @ W2 + b2
    gemm_tf32_kernel<2><<<dim3(DD / 128, MT / 128), 256>>>(phid, W2, b2, input, ppre, MT, DD, FFNH);
    // 10. LayerNorm
    ln_kernel<<<MT, 128>>>(ppre, gamma, beta, out);
}

// round 5
// speedup vs baseline: 1.7893x; 1.7893x over previous
#include <cuda_runtime.h>
#include <math.h>
#include <stdint.h>

// ---------------- problem constants ----------------
constexpr int BB   = 16;
constexpr int PP   = 2048;
constexpr int DD   = 512;
constexpr int MT   = BB * PP;      // 32768 rows

// ---------------- scratch (device globals, alloc-free) ----------------
// fragment-packed tf32 operands
__device__ float g_Ain[(size_t)MT * 512];        // 64 MB  input  A-frag (K=512)
__device__ float g_A1 [(size_t)MT * 1024];       // 128 MB ffn_in A-frag (K=1024)
__device__ float g_A2 [(size_t)MT * 4096];       // 512 MB hid    A-frag (K=4096)
__device__ float g_Bv [(size_t)512 * 512];       // Wv  B-frag
__device__ float g_B1 [(size_t)1024 * 4096];     // W1  B-frag
__device__ float g_B2 [(size_t)4096 * 512];      // W2  B-frag
// fp32 scratch
__device__ float g_q    [(size_t)MT * DD];
__device__ float g_aff  [(size_t)BB * 8 * 64 * PP];
__device__ float g_c2p  [(size_t)BB * 8 * 64 * PP];
__device__ float g_p2c  [(size_t)BB * 8 * 64 * PP];
__device__ float g_vcore[(size_t)BB * 8 * 64 * 64];
__device__ float g_vout [(size_t)MT * DD];
__device__ float g_pre  [(size_t)MT * DD];

// ---------------- helpers ----------------
__device__ __forceinline__ float to_tf32(float x) {
    unsigned u;
    asm("cvt.rna.tf32.f32 %0, %1;" : "=r"(u) : "f"(x));
    return __uint_as_float(u);
}
__device__ __forceinline__ uint32_t smem_u32(const void* p) {
    uint32_t a;
    asm("{ .reg .u64 t; cvta.to.shared.u64 t, %1; cvt.u32.u64 %0, t; }" : "=r"(a) : "l"(p));
    return a;
}
__device__ __forceinline__ void cp16(uint32_t d, const void* s) {
    asm volatile("cp.async.cg.shared.global [%0], [%1], 16;" :: "r"(d), "l"(s));
}
#define CP_COMMIT() asm volatile("cp.async.commit_group;" ::: "memory")
#define CP_WAIT2()  asm volatile("cp.async.wait_group 2;" ::: "memory")

__device__ __forceinline__ void mma_tf32(float d[4], const float a[4], float b0, float b1) {
    asm volatile(
        "mma.sync.aligned.m16n8k8.row.col.f32.tf32.tf32.f32 "
        "{%0,%1,%2,%3}, {%4,%5,%6,%7}, {%8,%9}, {%0,%1,%2,%3};\n"
        : "+f"(d[0]), "+f"(d[1]), "+f"(d[2]), "+f"(d[3])
        : "r"(__float_as_uint(a[0])), "r"(__float_as_uint(a[1])),
          "r"(__float_as_uint(a[2])), "r"(__float_as_uint(a[3])),
          "r"(__float_as_uint(b0)), "r"(__float_as_uint(b1)));
}
__device__ __forceinline__ float gelu_f(float x) {
    return 0.5f * x * (1.0f + erff(x * 0.70710678118654752f));
}

// ================= fragment-packed tf32 GEMM =================
// CTA tile 256m x 128n, K-step 16. 512 threads = 16 warps (wm 0..7, wn 0..1),
// warp tile 32m x 64n. A-frag: per (mtile,kt) 4096 floats
//   [wm][kk][mt][lane][e] ; e: a0=(m0,k0) a1=(m0+8,k0) a2=(m0,k0+4) a3=(m0+8,k0+4)
//   m0 = mtile*256+wm*32+mt*16+g, k0 = kt*16+kk*8+tig, lane=g*4+tig
// B-frag: per (ntile,kt) 2048 floats
//   [wn][kk][ntp][lane][e] ; e: {(k0,n0),(k0+4,n0),(k0,n0+8),(k0+4,n0+8)}
//   n0 = ntile*128+wn*64+ntp*16+g
// EPI 0: +bias -> fp32 row-major (width 512)
// EPI 1: +bias, GELU, tf32-round -> A-frag of GEMM2 (K2=4096, KT2=256)
// EPI 2: +bias +res -> fp32 row-major (width 512)
template <int EPI>
__global__ __launch_bounds__(512, 1) void gemm_frag(
    const float* __restrict__ Af, const float* __restrict__ Bf,
    const float* __restrict__ bias, const float* __restrict__ res,
    float* __restrict__ outF, float* __restrict__ outX, int KT)
{
    extern __shared__ float sm[];   // 4 stages * 6144 floats (A 4096 + B 2048)
    const int tid = threadIdx.x, warp = tid >> 5, lane = tid & 31;
    const int wm = warp & 7, wn = warp >> 3;
    const int g = lane >> 2, tig = lane & 3;
    const int ntile = blockIdx.x, mtile = blockIdx.y;
    const float* Ab = Af + (size_t)mtile * KT * 4096;
    const float* Bb = Bf + (size_t)ntile * KT * 2048;
    const uint32_t smb = smem_u32(sm);

    float acc[2][8][4];
#pragma unroll
    for (int mt = 0; mt < 2; mt++)
#pragma unroll
        for (int nt = 0; nt < 8; nt++)
#pragma unroll
            for (int r = 0; r < 4; r++) acc[mt][nt][r] = 0.0f;

    // prologue: fill 3 stages
#pragma unroll
    for (int s = 0; s < 3; s++) {
        uint32_t d = smb + s * 24576u;
        const float4* sa = (const float4*)(Ab + (size_t)s * 4096);
        cp16(d + tid * 16u, sa + tid);
        cp16(d + (tid + 512) * 16u, sa + tid + 512);
        const float4* sb = (const float4*)(Bb + (size_t)s * 2048);
        cp16(d + 16384u + tid * 16u, sb + tid);
        CP_COMMIT();
    }

    for (int kt = 0; kt < KT; kt++) {
        CP_WAIT2();
        __syncthreads();
        if (kt + 3 < KT) {
            uint32_t d = smb + ((kt + 3) & 3) * 24576u;
            const float4* sa = (const float4*)(Ab + (size_t)(kt + 3) * 4096);
            cp16(d + tid * 16u, sa + tid);
            cp16(d + (tid + 512) * 16u, sa + tid + 512);
            const float4* sb = (const float4*)(Bb + (size_t)(kt + 3) * 2048);
            cp16(d + 16384u + tid * 16u, sb + tid);
            CP_COMMIT();
        }
        const float* As = sm + (kt & 3) * 6144;
        const float* Bs = As + 4096;
#pragma unroll
        for (int kk = 0; kk < 2; kk++) {
            float af[2][4];
            *(float4*)af[0] = *(const float4*)(As + ((wm * 2 + kk) * 2 + 0) * 128 + lane * 4);
            *(float4*)af[1] = *(const float4*)(As + ((wm * 2 + kk) * 2 + 1) * 128 + lane * 4);
            float4 bv[4];
#pragma unroll
            for (int p = 0; p < 4; p++)
                bv[p] = *(const float4*)(Bs + ((wn * 2 + kk) * 4 + p) * 128 + lane * 4);
#pragma unroll
            for (int mt = 0; mt < 2; mt++)
#pragma unroll
                for (int p = 0; p < 4; p++) {
                    mma_tf32(acc[mt][2 * p],     af[mt], bv[p].x, bv[p].y);
                    mma_tf32(acc[mt][2 * p + 1], af[mt], bv[p].z, bv[p].w);
                }
        }
    }

    // ---------------- epilogue ----------------
#pragma unroll
    for (int mt = 0; mt < 2; mt++) {
#pragma unroll
        for (int nt = 0; nt < 8; nt++) {
            const int m0 = mtile * 256 + wm * 32 + mt * 16 + g;
            const int n0 = ntile * 128 + wn * 64 + nt * 8 + tig * 2;
            const float b0 = bias[n0], b1 = bias[n0 + 1];
            float v00 = acc[mt][nt][0] + b0, v01 = acc[mt][nt][1] + b1;
            float v10 = acc[mt][nt][2] + b0, v11 = acc[mt][nt][3] + b1;
            if (EPI == 0 || EPI == 2) {
                if (EPI == 2) {
                    const float2 r0 = *(const float2*)(res + (size_t)m0 * 512 + n0);
                    const float2 r1 = *(const float2*)(res + (size_t)(m0 + 8) * 512 + n0);
                    v00 += r0.x; v01 += r0.y; v10 += r1.x; v11 += r1.y;
                }
                *(float2*)(outF + (size_t)m0 * 512 + n0)       = make_float2(v00, v01);
                *(float2*)(outF + (size_t)(m0 + 8) * 512 + n0) = make_float2(v10, v11);
            } else {
                // scatter into GEMM2 A-frag (K2=4096, KT2=256); k coordinate = n0
                v00 = to_tf32(gelu_f(v00)); v01 = to_tf32(gelu_f(v01));
                v10 = to_tf32(gelu_f(v10)); v11 = to_tf32(gelu_f(v11));
                const int k0 = n0;
                const int kt2 = k0 >> 4, kk2 = (k0 >> 3) & 1;
                const int wm2 = (m0 >> 5) & 7, mt2 = (m0 >> 4) & 1;
                const int lane2 = (m0 & 7) * 4 + (k0 & 3);
                const int e2 = ((k0 >> 2) & 1) * 2;   // m0 bit3 = 0 here
                size_t X = ((((((size_t)mtile * 256 + kt2) * 8 + wm2) * 2 + kk2) * 2 + mt2) * 32 + lane2) * 4 + e2;
                outX[X]     = v00;   // (m0,   k0)
                outX[X + 4] = v01;   // (m0,   k0+1)  lane2+1
                outX[X + 1] = v10;   // (m0+8, k0)    e bit0
                outX[X + 5] = v11;   // (m0+8, k0+1)
            }
        }
    }
}

// ================= conversion kernels -> fragment layouts =================
// input (row-major [M][512]) -> A-frag, KT=32
__global__ __launch_bounds__(256) void conv_inA(const float* __restrict__ in, float* __restrict__ out) {
    int f = blockIdx.x * 256 + threadIdx.x;    // float4 index
    int lane = f & 31; int t = f >> 5;
    int mt = t & 1; t >>= 1; int kk = t & 1; t >>= 1; int wm = t & 7; t >>= 3;
    int kt = t & 31; int mtile = t >> 5;
    int gg = lane >> 2, tg = lane & 3;
    int m0 = mtile * 256 + wm * 32 + mt * 16 + gg;
    int k0 = kt * 16 + kk * 8 + tg;
    float4 v;
    v.x = to_tf32(in[(size_t)m0 * 512 + k0]);
    v.y = to_tf32(in[(size_t)(m0 + 8) * 512 + k0]);
    v.z = to_tf32(in[(size_t)m0 * 512 + k0 + 4]);
    v.w = to_tf32(in[(size_t)(m0 + 8) * 512 + k0 + 4]);
    ((float4*)out)[f] = v;
}

// ffn_in = [input - vout, vout] -> A-frag, K=1024, KT=64
__global__ __launch_bounds__(256) void conv_ffnA(const float* __restrict__ in, const float* __restrict__ vout,
                                                 float* __restrict__ out) {
    int f = blockIdx.x * 256 + threadIdx.x;
    int lane = f & 31; int t = f >> 5;
    int mt = t & 1; t >>= 1; int kk = t & 1; t >>= 1; int wm = t & 7; t >>= 3;
    int kt = t & 63; int mtile = t >> 6;
    int gg = lane >> 2, tg = lane & 3;
    int m0 = mtile * 256 + wm * 32 + mt * 16 + gg;
    int k0 = kt * 16 + kk * 8 + tg;
    float vv[4];
#pragma unroll
    for (int e = 0; e < 4; e++) {
        int m = m0 + (e & 1) * 8;
        int k = k0 + (e >> 1) * 4;
        float x;
        if (k < 512) x = in[(size_t)m * 512 + k] - vout[(size_t)m * 512 + k];
        else         x = vout[(size_t)m * 512 + (k - 512)];
        vv[e] = to_tf32(x);
    }
    ((float4*)out)[f] = make_float4(vv[0], vv[1], vv[2], vv[3]);
}

// W row-major [K][N] -> B-frag
__global__ __launch_bounds__(256) void conv_W(const float* __restrict__ W, float* __restrict__ out,
                                              int N, int KT) {
    int f = blockIdx.x * 256 + threadIdx.x;
    int lane = f & 31; int t = f >> 5;
    int ntp = t & 3; t >>= 2; int kk = t & 1; t >>= 1; int wn = t & 1; t >>= 1;
    int kt = t % KT; int ntile = t / KT;
    int gg = lane >> 2, tg = lane & 3;
    int n0 = ntile * 128 + wn * 64 + ntp * 16 + gg;
    int k0 = kt * 16 + kk * 8 + tg;
    float4 v;
    v.x = to_tf32(W[(size_t)k0 * N + n0]);
    v.y = to_tf32(W[(size_t)(k0 + 4) * N + n0]);
    v.z = to_tf32(W[(size_t)k0 * N + n0 + 8]);
    v.w = to_tf32(W[(size_t)(k0 + 4) * N + n0 + 8]);
    ((float4*)out)[f] = v;
}

// ================= attention chain (unchanged, proven in R1) =================
__global__ __launch_bounds__(256) void aff_kernel(
    const float* __restrict__ q, const float* __restrict__ cores, float* __restrict__ aff)
{
    __shared__ __align__(16) float cs[64][68];
    __shared__ __align__(16) float qs[64][68];
    const int bh = blockIdx.y, b = bh >> 3, h = bh & 7;
    const int p0 = blockIdx.x << 6;
    const int t = threadIdx.x;
#pragma unroll
    for (int i = 0; i < 4; i++) {
        int v = t + (i << 8);
        int r = v >> 4, c4 = (v & 15) << 2;
        *(float4*)&cs[r][c4] = *(const float4*)(cores + ((h * 64 + r) * 64 + c4));
        *(float4*)&qs[r][c4] = *(const float4*)(q + (size_t)(b * 2048 + p0 + r) * 512 + h * 64 + c4);
    }
    __syncthreads();
    const int c4 = (t >> 4) << 2, p4 = (t & 15) << 2;
    float acc[4][4] = {};
#pragma unroll
    for (int k = 0; k < 64; k++) {
        float a[4], bq[4];
#pragma unroll
        for (int i = 0; i < 4; i++) { a[i] = cs[c4 + i][k]; bq[i] = qs[p4 + i][k]; }
#pragma unroll
        for (int i = 0; i < 4; i++)
#pragma unroll
            for (int jx = 0; jx < 4; jx++) acc[i][jx] += a[i] * bq[jx];
    }
#pragma unroll
    for (int i = 0; i < 4; i++)
        *(float4*)(aff + (size_t)(bh * 64 + c4 + i) * 2048 + p0 + p4) =
            make_float4(acc[i][0] * 0.125f, acc[i][1] * 0.125f, acc[i][2] * 0.125f, acc[i][3] * 0.125f);
}

__global__ __launch_bounds__(256) void softmax_p_kernel(const float* __restrict__ aff, float* __restrict__ out)
{
    const int row = blockIdx.x;
    const int t = threadIdx.x, lane = t & 31, warp = t >> 5;
    const float4* src = (const float4*)(aff + (size_t)row * 2048);
    float4* dst = (float4*)(out + (size_t)row * 2048);
    __shared__ float red[8];
    float4 x0 = src[t], x1 = src[t + 256];
    float m = fmaxf(fmaxf(fmaxf(x0.x, x0.y), fmaxf(x0.z, x0.w)),
                    fmaxf(fmaxf(x1.x, x1.y), fmaxf(x1.z, x1.w)));
#pragma unroll
    for (int o = 16; o; o >>= 1) m = fmaxf(m, __shfl_xor_sync(0xffffffffu, m, o));
    if (lane == 0) red[warp] = m;
    __syncthreads();
    float M = red[0];
#pragma unroll
    for (int w = 1; w < 8; w++) M = fmaxf(M, red[w]);
    __syncthreads();
    float4 e0, e1;
    e0.x = expf(x0.x - M); e0.y = expf(x0.y - M); e0.z = expf(x0.z - M); e0.w = expf(x0.w - M);
    e1.x = expf(x1.x - M); e1.y = expf(x1.y - M); e1.z = expf(x1.z - M); e1.w = expf(x1.w - M);
    float s = e0.x + e0.y + e0.z + e0.w + e1.x + e1.y + e1.z + e1.w;
#pragma unroll
    for (int o = 16; o; o >>= 1) s += __shfl_xor_sync(0xffffffffu, s, o);
    if (lane == 0) red[warp] = s;
    __syncthreads();
    float S = 0.0f;
#pragma unroll
    for (int w = 0; w < 8; w++) S += red[w];
    float inv = 1.0f / S;
    dst[t]       = make_float4(e0.x * inv, e0.y * inv, e0.z * inv, e0.w * inv);
    dst[t + 256] = make_float4(e1.x * inv, e1.y * inv, e1.z * inv, e1.w * inv);
}

__global__ __launch_bounds__(256) void softmax_c_kernel(const float* __restrict__ aff, float* __restrict__ out)
{
    const int bh = blockIdx.y;
    const int p = (blockIdx.x << 8) + threadIdx.x;
    const float* src = aff + (size_t)bh * 64 * 2048 + p;
    float* dst = out + (size_t)bh * 64 * 2048 + p;
    float vals[64];
    float m = -1e30f;
#pragma unroll
    for (int c = 0; c < 64; c++) { vals[c] = src[c * 2048]; m = fmaxf(m, vals[c]); }
    float s = 0.0f;
#pragma unroll
    for (int c = 0; c < 64; c++) { vals[c] = expf(vals[c] - m); s += vals[c]; }
    float inv = 1.0f / s;
#pragma unroll
    for (int c = 0; c < 64; c++) dst[c * 2048] = vals[c] * inv;
}

__global__ __launch_bounds__(256) void vcore_kernel(
    const float* __restrict__ input, const float* __restrict__ c2p, float* __restrict__ vcore)
{
    __shared__ __align__(16) float a_s[64][68];
    __shared__ __align__(16) float v_s[64][68];
    const int bh = blockIdx.x, b = bh >> 3, h = bh & 7;
    const int t = threadIdx.x;
    const int c4 = (t >> 4) << 2, d4 = (t & 15) << 2;
    float acc[4][4] = {};
    for (int pt = 0; pt < 2048; pt += 64) {
#pragma unroll
        for (int i = 0; i < 4; i++) {
            int v = t + (i << 8);
            int r = v >> 4, k4 = (v & 15) << 2;
            *(float4*)&a_s[r][k4] = *(const float4*)(c2p + (size_t)(bh * 64 + r) * 2048 + pt + k4);
            *(float4*)&v_s[r][k4] = *(const float4*)(input + (size_t)(b * 2048 + pt + r) * 512 + h * 64 + k4);
        }
        __syncthreads();
#pragma unroll
        for (int k = 0; k < 64; k++) {
            float a[4], vv[4];
#pragma unroll
            for (int i = 0; i < 4; i++) { a[i] = a_s[c4 + i][k]; vv[i] = v_s[k][d4 + i]; }
#pragma unroll
            for (int i = 0; i < 4; i++)
#pragma unroll
                for (int jx = 0; jx < 4; jx++) acc[i][jx] += a[i] * vv[jx];
        }
        __syncthreads();
    }
#pragma unroll
    for (int i = 0; i < 4; i++)
        *(float4*)(vcore + (size_t)(bh * 64 + c4 + i) * 64 + d4) =
            make_float4(acc[i][0], acc[i][1], acc[i][2], acc[i][3]);
}

__global__ __launch_bounds__(256) void vpatch_kernel(
    const float* __restrict__ vcore, const float* __restrict__ p2c, float* __restrict__ vout)
{
    __shared__ __align__(16) float vc_s[64][68];
    __shared__ __align__(16) float pc_s[64][68];
    const int bh = blockIdx.y, b = bh >> 3, h = bh & 7;
    const int p0 = blockIdx.x << 6;
    const int t = threadIdx.x;
#pragma unroll
    for (int i = 0; i < 4; i++) {
        int v = t + (i << 8);
        int r = v >> 4, k4 = (v & 15) << 2;
        *(float4*)&vc_s[r][k4] = *(const float4*)(vcore + (size_t)(bh * 64 + r) * 64 + k4);
        *(float4*)&pc_s[r][k4] = *(const float4*)(p2c + (size_t)(bh * 64 + r) * 2048 + p0 + k4);
    }
    __syncthreads();
    const int p4 = (t & 15) << 2, d4 = (t >> 4) << 2;
    float acc[4][4] = {};
#pragma unroll
    for (int c = 0; c < 64; c++) {
        float a[4], vv[4];
#pragma unroll
        for (int i = 0; i < 4; i++) { a[i] = pc_s[c][p4 + i]; vv[i] = vc_s[c][d4 + i]; }
#pragma unroll
        for (int i = 0; i < 4; i++)
#pragma unroll
            for (int jx = 0; jx < 4; jx++) acc[i][jx] += a[i] * vv[jx];
    }
#pragma unroll
    for (int i = 0; i < 4; i++)
        *(float4*)(vout + (size_t)(b * 2048 + p0 + p4 + i) * 512 + h * 64 + d4) =
            make_float4(acc[i][0], acc[i][1], acc[i][2], acc[i][3]);
}

__global__ __launch_bounds__(128) void ln_kernel(
    const float* __restrict__ pre, const float* __restrict__ gamma,
    const float* __restrict__ beta, float* __restrict__ out)
{
    const int row = blockIdx.x;
    const int t = threadIdx.x, lane = t & 31, warp = t >> 5;
    __shared__ float rs[4], rs2[4];
    float4 x = *(const float4*)(pre + (size_t)row * 512 + t * 4);
    float s = x.x + x.y + x.z + x.w;
    float s2 = x.x * x.x + x.y * x.y + x.z * x.z + x.w * x.w;
#pragma unroll
    for (int o = 16; o; o >>= 1) {
        s  += __shfl_xor_sync(0xffffffffu, s, o);
        s2 += __shfl_xor_sync(0xffffffffu, s2, o);
    }
    if (lane == 0) { rs[warp] = s; rs2[warp] = s2; }
    __syncthreads();
    float S = rs[0] + rs[1] + rs[2] + rs[3];
    float S2 = rs2[0] + rs2[1] + rs2[2] + rs2[3];
    float mean = S * (1.0f / 512.0f);
    float var = S2 * (1.0f / 512.0f) - mean * mean;
    float rstd = rsqrtf(var + 1e-5f);
    float4 gm = *(const float4*)(gamma + t * 4);
    float4 bt = *(const float4*)(beta + t * 4);
    float4 o;
    o.x = (x.x - mean) * rstd * gm.x + bt.x;
    o.y = (x.y - mean) * rstd * gm.y + bt.y;
    o.z = (x.z - mean) * rstd * gm.z + bt.z;
    o.w = (x.w - mean) * rstd * gm.w + bt.w;
    *(float4*)(out + (size_t)row * 512 + t * 4) = o;
}

// ================= launch =================
extern "C" void kernel_launch(void* const* d_in, const int* in_sizes, int n_in,
                              void* d_out, int out_size)
{
    (void)in_sizes; (void)n_in; (void)out_size;
    const float* input = (const float*)d_in[0];
    const float* cores = (const float*)d_in[1];
    const float* Wv    = (const float*)d_in[2];
    const float* bv    = (const float*)d_in[3];
    const float* W1    = (const float*)d_in[4];
    const float* b1    = (const float*)d_in[5];
    const float* W2    = (const float*)d_in[6];
    const float* b2    = (const float*)d_in[7];
    const float* gamma = (const float*)d_in[8];
    const float* beta  = (const float*)d_in[9];
    float* out = (float*)d_out;

    float *pAin, *pA1, *pA2, *pBv, *pB1, *pB2;
    float *pq, *paff, *pc2p, *pp2c, *pvc, *pvo, *ppre;
    cudaGetSymbolAddress((void**)&pAin, g_Ain);
    cudaGetSymbolAddress((void**)&pA1, g_A1);
    cudaGetSymbolAddress((void**)&pA2, g_A2);
    cudaGetSymbolAddress((void**)&pBv, g_Bv);
    cudaGetSymbolAddress((void**)&pB1, g_B1);
    cudaGetSymbolAddress((void**)&pB2, g_B2);
    cudaGetSymbolAddress((void**)&pq, g_q);
    cudaGetSymbolAddress((void**)&paff, g_aff);
    cudaGetSymbolAddress((void**)&pc2p, g_c2p);
    cudaGetSymbolAddress((void**)&pp2c, g_p2c);
    cudaGetSymbolAddress((void**)&pvc, g_vcore);
    cudaGetSymbolAddress((void**)&pvo, g_vout);
    cudaGetSymbolAddress((void**)&ppre, g_pre);

    const int SMEM = 98304;   // 4 stages * 24 KB
    cudaFuncSetAttribute(gemm_frag<0>, cudaFuncAttributeMaxDynamicSharedMemorySize, SMEM);
    cudaFuncSetAttribute(gemm_frag<1>, cudaFuncAttributeMaxDynamicSharedMemorySize, SMEM);
    cudaFuncSetAttribute(gemm_frag<2>, cudaFuncAttributeMaxDynamicSharedMemorySize, SMEM);

    // operand conversions -> fragment layouts
    conv_W<<<256, 256>>>(Wv, pBv, 512, 32);          // 512*512/4/256
    conv_W<<<4096, 256>>>(W1, pB1, 4096, 64);        // 1024*4096/4/256
    conv_W<<<2048, 256>>>(W2, pB2, 512, 256);        // 4096*512/4/256
    conv_inA<<<16384, 256>>>(input, pAin);           // 32768*512/4/256

    // 1. q = input @ Wv + bv
    gemm_frag<0><<<dim3(4, 128), 512, SMEM>>>(pAin, pBv, bv, nullptr, pq, nullptr, 32);
    // 2-6. attention chain
    aff_kernel<<<dim3(PP / 64, BB * 8), 256>>>(pq, cores, paff);
    softmax_p_kernel<<<BB * 8 * 64, 256>>>(paff, pc2p);
    softmax_c_kernel<<<dim3(PP / 256, BB * 8), 256>>>(paff, pp2c);
    vcore_kernel<<<BB * 8, 256>>>(input, pc2p, pvc);
    vpatch_kernel<<<dim3(PP / 64, BB * 8), 256>>>(pvc, pp2c, pvo);
    // 7. ffn_in -> A-frag
    conv_ffnA<<<32768, 256>>>(input, pvo, pA1);      // 32768*1024/4/256
    // 8. hid = gelu(ffn_in @ W1 + b1) -> A-frag of GEMM2
    gemm_frag<1><<<dim3(32, 128), 512, SMEM>>>(pA1, pB1, b1, nullptr, nullptr, pA2, 64);
    // 9. pre = input + hid @ W2 + b2
    gemm_frag<2><<<dim3(4, 128), 512, SMEM>>>(pA2, pB2, b2, input, ppre, nullptr, 256);
    // 10. LayerNorm
    ln_kernel<<<MT, 128>>>(ppre, gamma, beta, out);
}